// round 5
// baseline (speedup 1.0000x reference)
#include <cuda_runtime.h>
#include <cstdint>

#define NN   4096
#define DD   16
#define BB   32
#define CI   32
#define CO   32
#define JTOT (BB*CI)     // 1024
#define KIO  (2*CI*CO)   // 2048

// ---------------- scratch ----------------
__device__ float g_P [(size_t)NN*NN];     // 64MB  tf32-rounded exp(relu(E E^T))
__device__ float g_rinv[NN];
__device__ float g_Y [(size_t)NN*JTOT];   // 16MB  P @ X (unnormalized)
__device__ float g_W [(size_t)NN*KIO];    // 32MB
__device__ float g_Xt[(size_t)JTOT*NN];   // 16MB  Xt[j][m] = tf32(x[b,m,c]), j=b*32+c

// ---------------- helpers ----------------
__device__ __forceinline__ uint32_t smem_u32(const void* p) {
    uint32_t a;
    asm("{ .reg .u64 t; cvta.to.shared.u64 t, %1; cvt.u32.u64 %0, t; }" : "=r"(a) : "l"(p));
    return a;
}
__device__ __forceinline__ float to_tf32(float v) {
    uint32_t u; asm("cvt.rna.tf32.f32 %0, %1;" : "=r"(u) : "f"(v));
    return __uint_as_float(u);
}
__device__ __forceinline__ float fast_exp_pos(float v) {
    float y = v * 1.4426950408889634f;
    int   i = (int)y;
    float f = y - (float)i;
    float p = 1.5252733804059838e-5f;
    p = fmaf(p, f, 1.5403530393381608e-4f);
    p = fmaf(p, f, 1.3333558146428443e-3f);
    p = fmaf(p, f, 9.6181291076284772e-3f);
    p = fmaf(p, f, 5.5504108664821580e-2f);
    p = fmaf(p, f, 2.4022650695910071e-1f);
    p = fmaf(p, f, 6.9314718055994531e-1f);
    p = fmaf(p, f, 1.0f);
    return p * __int_as_float((i + 127) << 23);
}
union F2 { float2 f; unsigned long long u; };
__device__ __forceinline__ F2 dup2(float v) { F2 r; asm("mov.b64 %0, {%1, %1};" : "=l"(r.u) : "f"(v)); return r; }
__device__ __forceinline__ void fma2(F2& c, F2 a, F2 b) {
    asm("fma.rn.f32x2 %0, %1, %2, %0;" : "+l"(c.u) : "l"(a.u), "l"(b.u));
}
__device__ __forceinline__ void cp16(uint32_t dst, const float* src) {
    asm volatile("cp.async.cg.shared.global [%0], [%1], 16;" :: "r"(dst), "l"(src));
}
__device__ __forceinline__ uint2 lds64(uint32_t addr) {
    uint2 v;
    asm volatile("ld.shared.v2.b32 {%0, %1}, [%2];" : "=r"(v.x), "=r"(v.y) : "r"(addr));
    return v;
}
__device__ __forceinline__ void mma_tf32(float* c, const uint32_t* a, const uint32_t* b) {
    asm volatile(
        "mma.sync.aligned.m16n8k8.row.col.f32.tf32.tf32.f32 "
        "{%0,%1,%2,%3}, {%4,%5,%6,%7}, {%8,%9}, {%0,%1,%2,%3};"
        : "+f"(c[0]), "+f"(c[1]), "+f"(c[2]), "+f"(c[3])
        : "r"(a[0]), "r"(a[1]), "r"(a[2]), "r"(a[3]), "r"(b[0]), "r"(b[1]));
}
#define SWZ128(off) ((off) ^ (((off) >> 3) & 0x70))

// ---------------- kernel 1: P = tf32(exp(relu(E E^T))), rinv ----------
__global__ void __launch_bounds__(256) k_supports(const float* __restrict__ E) {
    __shared__ float es[4][DD];
    __shared__ float wsum[4][8];
    const int tid = threadIdx.x;
    const int n0  = blockIdx.x * 4;

    if (tid < 4*DD) es[tid >> 4][tid & 15] = E[n0*DD + tid];
    __syncthreads();
    float ereg[4][DD];
    #pragma unroll
    for (int r = 0; r < 4; r++)
        #pragma unroll
        for (int d = 0; d < DD; d++) ereg[r][d] = es[r][d];

    float sum[4] = {0.f, 0.f, 0.f, 0.f};
    for (int m = tid; m < NN; m += 256) {
        const float4* em4 = reinterpret_cast<const float4*>(E + (size_t)m*DD);
        float4 q0 = em4[0], q1 = em4[1], q2 = em4[2], q3 = em4[3];
        float av[DD] = {q0.x,q0.y,q0.z,q0.w, q1.x,q1.y,q1.z,q1.w,
                        q2.x,q2.y,q2.z,q2.w, q3.x,q3.y,q3.z,q3.w};
        #pragma unroll
        for (int r = 0; r < 4; r++) {
            float d = 0.f;
            #pragma unroll
            for (int t = 0; t < DD; t++) d = fmaf(av[t], ereg[r][t], d);
            d = fmaxf(d, 0.f);
            float p = to_tf32(fast_exp_pos(d));
            g_P[(size_t)(n0 + r)*NN + m] = p;
            sum[r] += p;
        }
    }
    #pragma unroll
    for (int r = 0; r < 4; r++) {
        float s = sum[r];
        #pragma unroll
        for (int o = 16; o > 0; o >>= 1) s += __shfl_xor_sync(0xffffffffu, s, o);
        if ((tid & 31) == 0) wsum[r][tid >> 5] = s;
    }
    __syncthreads();
    if (tid < 4) {
        float t = 0.f;
        #pragma unroll
        for (int w = 0; w < 8; w++) t += wsum[tid][w];
        g_rinv[n0 + tid] = 1.0f / t;
    }
}

// ---------------- kernel 1b: Xt[j][m] = tf32(x[b,m,c]) ----------------
__global__ void __launch_bounds__(256) k_tr(const float* __restrict__ x) {
    __shared__ float s[32*33];
    const int tid = threadIdx.x;
    const int b   = blockIdx.y;
    const int m0  = blockIdx.x * 32;
    #pragma unroll
    for (int q = 0; q < 4; q++) {
        int idx = tid + q*256;
        int m = idx >> 5, c = idx & 31;
        s[c*33 + m] = to_tf32(x[(size_t)b*NN*CI + (size_t)(m0 + m)*CI + c]);
    }
    __syncthreads();
    #pragma unroll
    for (int q = 0; q < 4; q++) {
        int idx = tid + q*256;
        int jl = idx >> 5, mo = idx & 31;
        g_Xt[(size_t)(b*32 + jl)*NN + m0 + mo] = s[jl*33 + mo];
    }
}

// ---------------- kernel 2: mma.sync tf32 GEMM  Y = P @ Xt^T ----------------
// CTA 128x256, BK=32, 4-stage cp.async, software-pipelined fragments.
#define NITER   (NN/32)          // 128
#define STAGEB  49152            // 16KB A + 32KB B
#define SM_DATA 1024
#define GSMEM   (SM_DATA + 4*STAGEB)   // 197632

__device__ __forceinline__ void issue_loads(uint32_t sbase, int stage, int n0, int col0,
                                            int k0, int tid) {
    const uint32_t sa = sbase + SM_DATA + stage*STAGEB;
    const uint32_t sb = sa + 16384;
    #pragma unroll
    for (int q = 0; q < 4; q++) {                      // A: 128 rows x 32 k
        int gid = tid + q*256;
        int row = gid >> 3, g = gid & 7;
        uint32_t off = row*128 + g*16;
        cp16(sa + SWZ128(off), g_P + (size_t)(n0 + row)*NN + k0 + g*4);
    }
    #pragma unroll
    for (int q = 0; q < 8; q++) {                      // B: 256 rows x 32 k
        int gid = tid + q*256;
        int row = gid >> 3, g = gid & 7;
        uint32_t off = row*128 + g*16;
        cp16(sb + SWZ128(off), g_Xt + (size_t)(col0 + row)*NN + k0 + g*4);
    }
    asm volatile("cp.async.commit_group;" ::: "memory");
}

__global__ void __launch_bounds__(256, 1) k_gemm() {
    extern __shared__ __align__(1024) uint8_t dsm[];
    const uint32_t sbase = smem_u32(dsm);
    const int tid  = threadIdx.x;
    const int wid  = tid >> 5;
    const int lane = tid & 31;
    const int col0 = blockIdx.x * 256;
    const int n0   = blockIdx.y * 128;

    const int wm = (wid >> 2) * 64;        // 0 / 64
    const int wn = (wid & 3) * 64;         // 0..192
    const int r   = lane >> 2;             // 0..7
    const int kg  = lane & 3;              // 0..3
    const int kgh = kg >> 1;               // 0..1
    const uint32_t lowoff = (kg & 1) * 8;

    // stage-relative fragment addresses
    uint32_t relA[8];  uint32_t mswA[4];
    #pragma unroll
    for (int t = 0; t < 4; t++) {
        int m = wm + t*16 + r;
        relA[t*2]   = (uint32_t)(m*128)       + lowoff;
        relA[t*2+1] = (uint32_t)((m+8)*128)   + lowoff;
        mswA[t]     = (uint32_t)((m & 7) << 4);
    }
    uint32_t relB[8];  uint32_t mswB[8];
    #pragma unroll
    for (int nt = 0; nt < 8; nt++) {
        int j = wn + nt*8 + r;
        relB[nt] = (uint32_t)(j*128) + 16384u + lowoff;
        mswB[nt] = (uint32_t)((j & 7) << 4);
    }

    float acc[4][8][4];
    #pragma unroll
    for (int t = 0; t < 4; t++)
        #pragma unroll
        for (int nt = 0; nt < 8; nt++)
            #pragma unroll
            for (int e = 0; e < 4; e++) acc[t][nt][e] = 0.f;

    uint32_t afr[2][4][4];
    uint32_t bfr[2][8][2];

    auto loadfrag = [&](int buf, uint32_t stagebase, int ks) {
        const uint32_t Koff = (uint32_t)((ks*2 + kgh) << 4);
        #pragma unroll
        for (int t = 0; t < 4; t++) {
            uint2 v0 = lds64(stagebase + relA[t*2]   + (Koff ^ mswA[t]));
            uint2 v1 = lds64(stagebase + relA[t*2+1] + (Koff ^ mswA[t]));
            afr[buf][t][0] = v0.x; afr[buf][t][1] = v1.x;
            afr[buf][t][2] = v0.y; afr[buf][t][3] = v1.y;
        }
        #pragma unroll
        for (int nt = 0; nt < 8; nt++) {
            uint2 w = lds64(stagebase + relB[nt] + (Koff ^ mswB[nt]));
            bfr[buf][nt][0] = w.x; bfr[buf][nt][1] = w.y;
        }
    };

    issue_loads(sbase, 0, n0, col0, 0,  tid);
    issue_loads(sbase, 1, n0, col0, 32, tid);
    issue_loads(sbase, 2, n0, col0, 64, tid);
    asm volatile("cp.async.wait_group 1;" ::: "memory");   // stages 0,1 resident
    __syncthreads();
    loadfrag(0, sbase + SM_DATA, 0);                       // iter0 ks0

    for (int i = 0; i < NITER; i++) {
        issue_loads(sbase, (i + 3) & 3, n0, col0, ((i + 3) & (NITER-1))*32, tid);
        const uint32_t cur = sbase + SM_DATA + (i & 3)*STAGEB;
        const uint32_t nxt = sbase + SM_DATA + ((i + 1) & 3)*STAGEB;

        #pragma unroll
        for (int ks = 0; ks < 4; ks++) {
            if (ks < 3)             loadfrag((ks + 1) & 1, cur, ks + 1);
            else if (i + 1 < NITER) loadfrag(0, nxt, 0);     // next iter ks0 (stage i+1 resident)
            #pragma unroll
            for (int t = 0; t < 4; t++)
                #pragma unroll
                for (int nt = 0; nt < 8; nt++)
                    mma_tf32(acc[t][nt], afr[ks & 1][t], bfr[ks & 1][nt]);
        }
        if (i + 1 < NITER) {
            asm volatile("cp.async.wait_group 1;" ::: "memory");  // stages i+1, i+2 resident
            __syncthreads();
        }
    }
    asm volatile("cp.async.wait_group 0;" ::: "memory");   // drain tail junk groups

    // epilogue: direct float2 stores to g_Y
    #pragma unroll
    for (int t = 0; t < 4; t++) {
        const int row = n0 + wm + t*16 + r;
        #pragma unroll
        for (int nt = 0; nt < 8; nt++) {
            const int col = col0 + wn + nt*8 + kg*2;
            *reinterpret_cast<float2*>(&g_Y[(size_t)row*JTOT + col]) =
                make_float2(acc[t][nt][0], acc[t][nt][1]);
            *reinterpret_cast<float2*>(&g_Y[(size_t)(row+8)*JTOT + col]) =
                make_float2(acc[t][nt][2], acc[t][nt][3]);
        }
    }
}

// ---------------- kernel 3: W[n][kio] = sum_d E[n][d] * wp[d][kio] ---------
__global__ void __launch_bounds__(256) k_wgen(const float* __restrict__ E,
                                              const float* __restrict__ wp) {
    const int col = blockIdx.x * 256 + threadIdx.x;
    const int n0  = blockIdx.y * 128;
    __shared__ float es[128 * DD];
    for (int t = threadIdx.x; t < 128*DD; t += 256) es[t] = E[n0*DD + t];
    float w[DD];
    #pragma unroll
    for (int d = 0; d < DD; d++) w[d] = wp[d*KIO + col];
    __syncthreads();
    #pragma unroll 4
    for (int n = 0; n < 128; n++) {
        float acc = 0.f;
        #pragma unroll
        for (int d = 0; d < DD; d++) acc = fmaf(es[n*DD + d], w[d], acc);
        g_W[(size_t)(n0 + n)*KIO + col] = acc;
    }
}

// ---------------- kernel 4: epilogue (f32x2, 4 chains) ---------------------
__global__ void __launch_bounds__(256) k_out(const float* __restrict__ x,
                                             const float* __restrict__ bp,
                                             const float* __restrict__ E,
                                             float* __restrict__ out) {
    const int n   = blockIdx.x;
    const int tid = threadIdx.x;
    __shared__ __align__(16) float ws[KIO];
    __shared__ __align__(16) float xs[JTOT];
    __shared__ __align__(16) float ys[JTOT];
    __shared__ float bsh[CO];

    {
        const float4* wsrc = reinterpret_cast<const float4*>(&g_W[(size_t)n*KIO]);
        float4* wdst = reinterpret_cast<float4*>(ws);
        wdst[tid]       = wsrc[tid];
        wdst[tid + 256] = wsrc[tid + 256];
        const float4* ysrc = reinterpret_cast<const float4*>(&g_Y[(size_t)n*JTOT]);
        reinterpret_cast<float4*>(ys)[tid] = ysrc[tid];
    }
    for (int t = tid; t < JTOT; t += 256) {
        int b = t >> 5, i = t & 31;
        xs[t] = x[(size_t)b*NN*CI + (size_t)n*CI + i];
    }
    if (tid < CO) {
        float acc = 0.f;
        #pragma unroll
        for (int d = 0; d < DD; d++) acc = fmaf(E[n*DD + d], bp[d*CO + tid], acc);
        bsh[tid] = acc;
    }
    __syncthreads();

    const float rinv = g_rinv[n];
    const int o2 = tid & 15;
    const int bq = tid >> 4;
    #pragma unroll
    for (int rep = 0; rep < 2; rep++) {
        const int b = bq + rep*16;
        F2 cx0, cx1, cy0, cy1;
        cx0.u = cx1.u = cy0.u = cy1.u = 0ull;
        #pragma unroll
        for (int i = 0; i < CI; i += 2) {
            F2 xv0 = dup2(xs[b*32 + i]);
            F2 xv1 = dup2(xs[b*32 + i + 1]);
            F2 yv0 = dup2(ys[b*32 + i]);
            F2 yv1 = dup2(ys[b*32 + i + 1]);
            F2 w00, w01, w10, w11;
            w00.f = *reinterpret_cast<const float2*>(&ws[i*32 + 2*o2]);
            w01.f = *reinterpret_cast<const float2*>(&ws[(i+1)*32 + 2*o2]);
            w10.f = *reinterpret_cast<const float2*>(&ws[1024 + i*32 + 2*o2]);
            w11.f = *reinterpret_cast<const float2*>(&ws[1024 + (i+1)*32 + 2*o2]);
            fma2(cx0, xv0, w00);
            fma2(cx1, xv1, w01);
            fma2(cy0, yv0, w10);
            fma2(cy1, yv1, w11);
        }
        const int o = 2*o2;
        float r0 = (cx0.f.x + cx1.f.x) + rinv*(cy0.f.x + cy1.f.x) + bsh[o];
        float r1 = (cx0.f.y + cx1.f.y) + rinv*(cy0.f.y + cy1.f.y) + bsh[o+1];
        *reinterpret_cast<float2*>(&out[(size_t)b*NN*CO + (size_t)n*CO + o]) = make_float2(r0, r1);
    }
}

// ---------------- launcher -------------------------------------------------
extern "C" void kernel_launch(void* const* d_in, const int* in_sizes, int n_in,
                              void* d_out, int out_size) {
    const float* x  = (const float*)d_in[0];
    const float* wp = (const float*)d_in[1];
    const float* bp = (const float*)d_in[2];
    const float* E  = (const float*)d_in[3];
    float* out = (float*)d_out;

    static bool attr_done = false;
    if (!attr_done) {
        cudaFuncSetAttribute(k_gemm, cudaFuncAttributeMaxDynamicSharedMemorySize, GSMEM);
        attr_done = true;
    }

    k_supports<<<NN/4, 256>>>(E);
    dim3 gt(NN/32, BB);
    k_tr<<<gt, 256>>>(x);
    dim3 gw(KIO/256, NN/128);
    k_wgen<<<gw, 256>>>(E, wp);
    dim3 gg(JTOT/256, NN/128);            // (4, 32) = 128 CTAs
    k_gemm<<<gg, 256, GSMEM>>>();
    k_out<<<NN, 256>>>(x, bp, E, out);
}

// round 6
// speedup vs baseline: 1.2883x; 1.2883x over previous
#include <cuda_runtime.h>
#include <cuda_fp16.h>
#include <cstdint>

#define NN   4096
#define DD   16
#define BB   32
#define CI   32
#define CO   32
#define JTOT (BB*CI)     // 1024
#define KIO  (2*CI*CO)   // 2048

// ---------------- scratch ----------------
__device__ float  g_P [(size_t)NN*NN];     // 64MB  fp32 relu(E E^T) logits (phase1 scratch)
__device__ __half g_Ph[(size_t)NN*NN];     // 32MB  fp16 exp(v - rowmax)
__device__ float  g_rinv[NN];              // 1/rowsum(exp(v - rowmax))
__device__ float  g_Y [(size_t)NN*JTOT];   // 16MB  Ph @ X (unnormalized)
__device__ float  g_W [(size_t)NN*KIO];    // 32MB
__device__ __half g_Xt[(size_t)JTOT*NN];   // 8MB   Xt[j][m] = fp16(x[b,m,c]), j=b*32+c

// ---------------- helpers ----------------
__device__ __forceinline__ uint32_t smem_u32(const void* p) {
    uint32_t a;
    asm("{ .reg .u64 t; cvta.to.shared.u64 t, %1; cvt.u32.u64 %0, t; }" : "=r"(a) : "l"(p));
    return a;
}
// exp(v) for v <= ~0 (and small positive), FFMA-only; i = floor so f in [0,1)
__device__ __forceinline__ float fast_exp(float v) {
    float y = v * 1.4426950408889634f;
    int   i = __float2int_rd(y);
    float f = y - (float)i;
    float p = 1.5252733804059838e-5f;
    p = fmaf(p, f, 1.5403530393381608e-4f);
    p = fmaf(p, f, 1.3333558146428443e-3f);
    p = fmaf(p, f, 9.6181291076284772e-3f);
    p = fmaf(p, f, 5.5504108664821580e-2f);
    p = fmaf(p, f, 2.4022650695910071e-1f);
    p = fmaf(p, f, 6.9314718055994531e-1f);
    p = fmaf(p, f, 1.0f);
    return p * __int_as_float((i + 127) << 23);
}
union F2 { float2 f; unsigned long long u; };
__device__ __forceinline__ F2 dup2(float v) { F2 r; asm("mov.b64 %0, {%1, %1};" : "=l"(r.u) : "f"(v)); return r; }
__device__ __forceinline__ void fma2(F2& c, F2 a, F2 b) {
    asm("fma.rn.f32x2 %0, %1, %2, %0;" : "+l"(c.u) : "l"(a.u), "l"(b.u));
}
__device__ __forceinline__ void cp16(uint32_t dst, const void* src) {
    asm volatile("cp.async.cg.shared.global [%0], [%1], 16;" :: "r"(dst), "l"(src));
}
__device__ __forceinline__ void ldm4(uint32_t* r, uint32_t addr) {
    asm volatile("ldmatrix.sync.aligned.m8n8.x4.shared.b16 {%0,%1,%2,%3}, [%4];"
                 : "=r"(r[0]), "=r"(r[1]), "=r"(r[2]), "=r"(r[3]) : "r"(addr));
}
__device__ __forceinline__ void mma_f16(float* c, const uint32_t* a, const uint32_t* b) {
    asm volatile(
        "mma.sync.aligned.m16n8k16.row.col.f32.f16.f16.f32 "
        "{%0,%1,%2,%3}, {%4,%5,%6,%7}, {%8,%9}, {%0,%1,%2,%3};"
        : "+f"(c[0]), "+f"(c[1]), "+f"(c[2]), "+f"(c[3])
        : "r"(a[0]), "r"(a[1]), "r"(a[2]), "r"(a[3]), "r"(b[0]), "r"(b[1]));
}
#define SWZ128(off) ((off) ^ (((off) >> 3) & 0x70))

// ---- kernel 1: logits -> rowmax -> Ph = fp16(exp(v-max)), rinv = 1/rowsum ----
__global__ void __launch_bounds__(256) k_supports(const float* __restrict__ E) {
    __shared__ float es[4*DD];
    __shared__ float red[4][8];
    __shared__ float rowmax[4];
    const int tid = threadIdx.x;
    const int n0  = blockIdx.x * 4;

    if (tid < 4*DD) es[tid] = E[n0*DD + tid];
    __syncthreads();
    float ereg[4][DD];
    #pragma unroll
    for (int r = 0; r < 4; r++)
        #pragma unroll
        for (int d = 0; d < DD; d++) ereg[r][d] = es[r*DD + d];

    // phase 1: logits + running max (2 adjacent m per thread)
    float mx[4] = {0.f, 0.f, 0.f, 0.f};
    for (int m2 = tid; m2 < NN/2; m2 += 256) {
        const float4* e4 = reinterpret_cast<const float4*>(E + (size_t)(2*m2)*DD);
        float4 u0 = e4[0], u1 = e4[1], u2 = e4[2], u3 = e4[3];
        float4 v0 = e4[4], v1 = e4[5], v2 = e4[6], v3 = e4[7];
        float a0[DD] = {u0.x,u0.y,u0.z,u0.w, u1.x,u1.y,u1.z,u1.w,
                        u2.x,u2.y,u2.z,u2.w, u3.x,u3.y,u3.z,u3.w};
        float a1[DD] = {v0.x,v0.y,v0.z,v0.w, v1.x,v1.y,v1.z,v1.w,
                        v2.x,v2.y,v2.z,v2.w, v3.x,v3.y,v3.z,v3.w};
        #pragma unroll
        for (int r = 0; r < 4; r++) {
            float d0 = 0.f, d1 = 0.f;
            #pragma unroll
            for (int t = 0; t < DD; t++) {
                d0 = fmaf(a0[t], ereg[r][t], d0);
                d1 = fmaf(a1[t], ereg[r][t], d1);
            }
            d0 = fmaxf(d0, 0.f); d1 = fmaxf(d1, 0.f);
            *reinterpret_cast<float2*>(&g_P[(size_t)(n0 + r)*NN + 2*m2]) = make_float2(d0, d1);
            mx[r] = fmaxf(mx[r], fmaxf(d0, d1));
        }
    }
    #pragma unroll
    for (int r = 0; r < 4; r++) {
        float s = mx[r];
        #pragma unroll
        for (int o = 16; o > 0; o >>= 1) s = fmaxf(s, __shfl_xor_sync(0xffffffffu, s, o));
        if ((tid & 31) == 0) red[r][tid >> 5] = s;
    }
    __syncthreads();
    if (tid < 4) {
        float t = red[tid][0];
        #pragma unroll
        for (int w = 1; w < 8; w++) t = fmaxf(t, red[tid][w]);
        rowmax[tid] = t;
    }
    __syncthreads();
    float rm[4];
    #pragma unroll
    for (int r = 0; r < 4; r++) rm[r] = rowmax[r];

    // phase 2: exp(v - max) -> fp16, rowsum  (logit rows are L2-hot)
    float sum[4] = {0.f, 0.f, 0.f, 0.f};
    for (int m2 = tid; m2 < NN/2; m2 += 256) {
        #pragma unroll
        for (int r = 0; r < 4; r++) {
            float2 d = *reinterpret_cast<const float2*>(&g_P[(size_t)(n0 + r)*NN + 2*m2]);
            float p0 = fast_exp(d.x - rm[r]);
            float p1 = fast_exp(d.y - rm[r]);
            __half2 h = __floats2half2_rn(p0, p1);
            *reinterpret_cast<__half2*>(&g_Ph[(size_t)(n0 + r)*NN + 2*m2]) = h;
            sum[r] += __half2float(__low2half(h)) + __half2float(__high2half(h));
        }
    }
    __syncthreads();
    #pragma unroll
    for (int r = 0; r < 4; r++) {
        float s = sum[r];
        #pragma unroll
        for (int o = 16; o > 0; o >>= 1) s += __shfl_xor_sync(0xffffffffu, s, o);
        if ((tid & 31) == 0) red[r][tid >> 5] = s;
    }
    __syncthreads();
    if (tid < 4) {
        float t = 0.f;
        #pragma unroll
        for (int w = 0; w < 8; w++) t += red[tid][w];
        g_rinv[n0 + tid] = 1.0f / t;
    }
}

// ---------------- kernel 1b: Xt[j][m] = fp16(x[b,m,c]) ----------------
__global__ void __launch_bounds__(256) k_tr(const float* __restrict__ x) {
    __shared__ float s[32*33];
    const int tid = threadIdx.x;
    const int b   = blockIdx.y;
    const int m0  = blockIdx.x * 32;
    #pragma unroll
    for (int q = 0; q < 4; q++) {
        int idx = tid + q*256;
        int m = idx >> 5, c = idx & 31;
        s[c*33 + m] = x[(size_t)b*NN*CI + (size_t)(m0 + m)*CI + c];
    }
    __syncthreads();
    #pragma unroll
    for (int q = 0; q < 2; q++) {
        int idx2 = tid + q*256;              // 512 half2 elems
        int jl = idx2 >> 4, mo2 = idx2 & 15;
        __half2 h = __floats2half2_rn(s[jl*33 + 2*mo2], s[jl*33 + 2*mo2 + 1]);
        *reinterpret_cast<__half2*>(&g_Xt[(size_t)(b*32 + jl)*NN + m0 + 2*mo2]) = h;
    }
}

// ------- kernel 2: fp16 mma.sync m16n8k16 GEMM  Y = Ph @ Xt^T -------
// CTA 128x256, BK=64 (halves), 4-stage cp.async, ldmatrix fragments.
#define NITER   (NN/64)          // 64
#define STAGEB  49152            // 16KB A (128x128B) + 32KB B (256x128B)
#define SM_DATA 1024
#define GSMEM   (SM_DATA + 4*STAGEB)   // 197632

__device__ __forceinline__ void issue_loads(uint32_t sbase, int stage, int n0, int col0,
                                            int k0, int tid) {
    const uint32_t sa = sbase + SM_DATA + stage*STAGEB;
    const uint32_t sb = sa + 16384;
    #pragma unroll
    for (int q = 0; q < 4; q++) {                      // A: 128 rows x 64 halves
        int gid = tid + q*256;
        int row = gid >> 3, g = gid & 7;
        uint32_t off = row*128 + g*16;
        cp16(sa + SWZ128(off), g_Ph + (size_t)(n0 + row)*NN + k0 + g*8);
    }
    #pragma unroll
    for (int q = 0; q < 8; q++) {                      // B: 256 rows x 64 halves
        int gid = tid + q*256;
        int row = gid >> 3, g = gid & 7;
        uint32_t off = row*128 + g*16;
        cp16(sb + SWZ128(off), g_Xt + (size_t)(col0 + row)*NN + k0 + g*8);
    }
    asm volatile("cp.async.commit_group;" ::: "memory");
}

__global__ void __launch_bounds__(256, 1) k_gemm() {
    extern __shared__ __align__(1024) uint8_t dsm[];
    const uint32_t sbase = smem_u32(dsm);
    const int tid  = threadIdx.x;
    const int wid  = tid >> 5;
    const int lane = tid & 31;
    const int col0 = blockIdx.x * 256;
    const int n0   = blockIdx.y * 128;

    const int wm = (wid >> 2) * 64;        // 0 / 64
    const int wn = (wid & 3) * 64;         // 0..192
    const int r   = lane >> 2;             // 0..7
    const int kg  = lane & 3;              // 0..3

    // ldmatrix lane addressing (stage-relative byte offsets)
    // A tile t (m16 x k16): lanes 0-7 rows+0..7/kc0, 8-15 rows+8..15/kc0, 16-23 +0..7/kc1, 24-31 +8..15/kc1
    uint32_t aBase[4], aXor[4];
    {
        int rl = (lane & 7) + ((lane >> 3) & 1) * 8;
        #pragma unroll
        for (int t = 0; t < 4; t++) {
            int row = wm + t*16 + rl;
            aBase[t] = (uint32_t)(row * 128);
            aXor[t]  = (uint32_t)((row & 7) << 4);
        }
    }
    const uint32_t aKc = (uint32_t)(((lane >> 4) & 1) * 16);
    // B pair p (two n8 tiles x k16): lanes 0-7 n+0..7/kc0, 8-15 n+0..7/kc1, 16-23 n+8..15/kc0, 24-31 n+8..15/kc1
    uint32_t bBase[4], bXor[4];
    {
        int jl = ((lane >> 4) & 1) * 8 + (lane & 7);
        #pragma unroll
        for (int p = 0; p < 4; p++) {
            int jr = wn + p*16 + jl;
            bBase[p] = 16384u + (uint32_t)(jr * 128);
            bXor[p]  = (uint32_t)((jr & 7) << 4);
        }
    }
    const uint32_t bKc = (uint32_t)(((lane >> 3) & 1) * 16);

    float acc[4][8][4];
    #pragma unroll
    for (int t = 0; t < 4; t++)
        #pragma unroll
        for (int nt = 0; nt < 8; nt++)
            #pragma unroll
            for (int e = 0; e < 4; e++) acc[t][nt][e] = 0.f;

    issue_loads(sbase, 0, n0, col0, 0,   tid);
    issue_loads(sbase, 1, n0, col0, 64,  tid);
    issue_loads(sbase, 2, n0, col0, 128, tid);

    for (int i = 0; i < NITER; i++) {
        asm volatile("cp.async.wait_group 2;" ::: "memory");
        __syncthreads();
        issue_loads(sbase, (i + 3) & 3, n0, col0, ((i + 3) & (NITER-1))*64, tid);

        const uint32_t cur = sbase + SM_DATA + (i & 3)*STAGEB;
        #pragma unroll
        for (int ks = 0; ks < 4; ks++) {               // 4 x k16 per BK=64
            const uint32_t ka = (uint32_t)(ks*32) + aKc;
            const uint32_t kb = (uint32_t)(ks*32) + bKc;
            uint32_t a[4][4];
            #pragma unroll
            for (int t = 0; t < 4; t++)
                ldm4(a[t], cur + aBase[t] + (ka ^ aXor[t]));
            uint32_t b[8][2];
            #pragma unroll
            for (int p = 0; p < 4; p++) {
                uint32_t rr[4];
                ldm4(rr, cur + bBase[p] + (kb ^ bXor[p]));
                b[2*p][0]   = rr[0]; b[2*p][1]   = rr[1];
                b[2*p+1][0] = rr[2]; b[2*p+1][1] = rr[3];
            }
            #pragma unroll
            for (int t = 0; t < 4; t++)
                #pragma unroll
                for (int nt = 0; nt < 8; nt++)
                    mma_f16(acc[t][nt], a[t], b[nt]);
        }
    }
    asm volatile("cp.async.wait_group 0;" ::: "memory");

    // epilogue: same C layout as m16n8k8 -> direct float2 stores
    #pragma unroll
    for (int t = 0; t < 4; t++) {
        const int row = n0 + wm + t*16 + r;
        #pragma unroll
        for (int nt = 0; nt < 8; nt++) {
            const int col = col0 + wn + nt*8 + kg*2;
            *reinterpret_cast<float2*>(&g_Y[(size_t)row*JTOT + col]) =
                make_float2(acc[t][nt][0], acc[t][nt][1]);
            *reinterpret_cast<float2*>(&g_Y[(size_t)(row+8)*JTOT + col]) =
                make_float2(acc[t][nt][2], acc[t][nt][3]);
        }
    }
}

// ---------------- kernel 3: W[n][kio] = sum_d E[n][d] * wp[d][kio] ---------
__global__ void __launch_bounds__(256) k_wgen(const float* __restrict__ E,
                                              const float* __restrict__ wp) {
    const int col = blockIdx.x * 256 + threadIdx.x;
    const int n0  = blockIdx.y * 128;
    __shared__ float es[128 * DD];
    for (int t = threadIdx.x; t < 128*DD; t += 256) es[t] = E[n0*DD + t];
    float w[DD];
    #pragma unroll
    for (int d = 0; d < DD; d++) w[d] = wp[d*KIO + col];
    __syncthreads();
    #pragma unroll 4
    for (int n = 0; n < 128; n++) {
        float acc = 0.f;
        #pragma unroll
        for (int d = 0; d < DD; d++) acc = fmaf(es[n*DD + d], w[d], acc);
        g_W[(size_t)(n0 + n)*KIO + col] = acc;
    }
}

// ---------------- kernel 4: epilogue (f32x2, 4 chains) ---------------------
__global__ void __launch_bounds__(256) k_out(const float* __restrict__ x,
                                             const float* __restrict__ bp,
                                             const float* __restrict__ E,
                                             float* __restrict__ out) {
    const int n   = blockIdx.x;
    const int tid = threadIdx.x;
    __shared__ __align__(16) float ws[KIO];
    __shared__ __align__(16) float xs[JTOT];
    __shared__ __align__(16) float ys[JTOT];
    __shared__ float bsh[CO];

    {
        const float4* wsrc = reinterpret_cast<const float4*>(&g_W[(size_t)n*KIO]);
        float4* wdst = reinterpret_cast<float4*>(ws);
        wdst[tid]       = wsrc[tid];
        wdst[tid + 256] = wsrc[tid + 256];
        const float4* ysrc = reinterpret_cast<const float4*>(&g_Y[(size_t)n*JTOT]);
        reinterpret_cast<float4*>(ys)[tid] = ysrc[tid];
    }
    for (int t = tid; t < JTOT; t += 256) {
        int b = t >> 5, i = t & 31;
        xs[t] = x[(size_t)b*NN*CI + (size_t)n*CI + i];
    }
    if (tid < CO) {
        float acc = 0.f;
        #pragma unroll
        for (int d = 0; d < DD; d++) acc = fmaf(E[n*DD + d], bp[d*CO + tid], acc);
        bsh[tid] = acc;
    }
    __syncthreads();

    const float rinv = g_rinv[n];
    const int o2 = tid & 15;
    const int bq = tid >> 4;
    #pragma unroll
    for (int rep = 0; rep < 2; rep++) {
        const int b = bq + rep*16;
        F2 cx0, cx1, cy0, cy1;
        cx0.u = cx1.u = cy0.u = cy1.u = 0ull;
        #pragma unroll
        for (int i = 0; i < CI; i += 2) {
            F2 xv0 = dup2(xs[b*32 + i]);
            F2 xv1 = dup2(xs[b*32 + i + 1]);
            F2 yv0 = dup2(ys[b*32 + i]);
            F2 yv1 = dup2(ys[b*32 + i + 1]);
            F2 w00, w01, w10, w11;
            w00.f = *reinterpret_cast<const float2*>(&ws[i*32 + 2*o2]);
            w01.f = *reinterpret_cast<const float2*>(&ws[(i+1)*32 + 2*o2]);
            w10.f = *reinterpret_cast<const float2*>(&ws[1024 + i*32 + 2*o2]);
            w11.f = *reinterpret_cast<const float2*>(&ws[1024 + (i+1)*32 + 2*o2]);
            fma2(cx0, xv0, w00);
            fma2(cx1, xv1, w01);
            fma2(cy0, yv0, w10);
            fma2(cy1, yv1, w11);
        }
        const int o = 2*o2;
        float r0 = (cx0.f.x + cx1.f.x) + rinv*(cy0.f.x + cy1.f.x) + bsh[o];
        float r1 = (cx0.f.y + cx1.f.y) + rinv*(cy0.f.y + cy1.f.y) + bsh[o+1];
        *reinterpret_cast<float2*>(&out[(size_t)b*NN*CO + (size_t)n*CO + o]) = make_float2(r0, r1);
    }
}

// ---------------- launcher -------------------------------------------------
extern "C" void kernel_launch(void* const* d_in, const int* in_sizes, int n_in,
                              void* d_out, int out_size) {
    const float* x  = (const float*)d_in[0];
    const float* wp = (const float*)d_in[1];
    const float* bp = (const float*)d_in[2];
    const float* E  = (const float*)d_in[3];
    float* out = (float*)d_out;

    static bool attr_done = false;
    if (!attr_done) {
        cudaFuncSetAttribute(k_gemm, cudaFuncAttributeMaxDynamicSharedMemorySize, GSMEM);
        attr_done = true;
    }

    k_supports<<<NN/4, 256>>>(E);
    dim3 gt(NN/32, BB);
    k_tr<<<gt, 256>>>(x);
    dim3 gw(KIO/256, NN/128);
    k_wgen<<<gw, 256>>>(E, wp);
    dim3 gg(JTOT/256, NN/128);            // (4, 32) = 128 CTAs
    k_gemm<<<gg, 256, GSMEM>>>();
    k_out<<<NN, 256>>>(x, bp, E, out);
}